// round 1
// baseline (speedup 1.0000x reference)
#include <cuda_runtime.h>

#define PI_F 3.14159265358979323846f

static __device__ __forceinline__ float f_rsqrt(float x){ float r; asm("rsqrt.approx.f32 %0, %1;" : "=f"(r) : "f"(x)); return r; }
static __device__ __forceinline__ float f_sqrt (float x){ float r; asm("sqrt.approx.f32 %0, %1;"  : "=f"(r) : "f"(x)); return r; }
static __device__ __forceinline__ float f_rcp  (float x){ float r; asm("rcp.approx.f32 %0, %1;"   : "=f"(r) : "f"(x)); return r; }

struct c32 { float x, y; };
static __device__ __forceinline__ c32 cmul(c32 a, c32 b){
    c32 r;
    r.x = fmaf(a.x, b.x, -a.y * b.y);
    r.y = fmaf(a.x, b.y,  a.y * b.x);
    return r;
}

// CNOT(control=c, target=tq) as index permutation: new[j] = old[perm(j)]
static __device__ __forceinline__ constexpr int cnotp(int j, int c, int tq){
    return j ^ (((j >> (3 - c)) & 1) << (3 - tq));
}

constexpr int THREADS  = 256;
constexpr int WARPS    = 8;
constexpr int BLOCKS   = 256;
constexpr int BATCH    = 65536;
constexpr int NCHUNKS  = BATCH / 32;   // 2048 chunks of 32 rows

__global__ __launch_bounds__(THREADS, 2)
void qp_kernel(const float* __restrict__ x,
               const float* __restrict__ pre_w,
               const float* __restrict__ pre_b,
               const float* __restrict__ qw,
               const float* __restrict__ post_w,
               const float* __restrict__ post_b,
               float* __restrict__ out)
{
    __shared__ float  wsm[4 * 1024];    // pre_w, qubit-major (as stored)
    __shared__ float  pwT[4 * 1024];    // post_w transposed: pwT[q][d]
    __shared__ float  pbs[1024];        // post_b
    __shared__ float2 rotm[4][4];       // Rot gate matrices (U00,U01,U10,U11)
    __shared__ float  pbq[4];           // pre_b
    __shared__ float4 zsm[WARPS * 32];  // per-warp z staging

    const int t = threadIdx.x;
    for (int i = t; i < 4096; i += THREADS) wsm[i] = pre_w[i];
    for (int i = t; i < 4096; i += THREADS) pwT[(i & 3) * 1024 + (i >> 2)] = post_w[i];
    for (int i = t; i < 1024; i += THREADS) pbs[i] = post_b[i];
    if (t < 4) {
        pbq[t] = pre_b[t];
        float phi = qw[t * 3 + 0], th = qw[t * 3 + 1], om = qw[t * 3 + 2];
        float st, ct; sincosf(0.5f * th,         &st, &ct);
        float sp, cp; sincosf(0.5f * (phi + om), &sp, &cp);
        float sm, cm; sincosf(0.5f * (phi - om), &sm, &cm);
        rotm[t][0] = make_float2( ct * cp, -ct * sp);   // e^{-i(phi+om)/2} cos
        rotm[t][1] = make_float2(-st * cm, -st * sm);   // -e^{ i(phi-om)/2} sin
        rotm[t][2] = make_float2( st * cm, -st * sm);   // e^{-i(phi-om)/2} sin
        rotm[t][3] = make_float2( ct * cp,  ct * sp);   // e^{ i(phi+om)/2} cos
    }
    __syncthreads();

    const int warp = t >> 5, lane = t & 31;
    const int gw = blockIdx.x * WARPS + warp;
    const int nw = gridDim.x * WARPS;
    const float4* __restrict__ x4  = (const float4*)x;
    float4* __restrict__ out4      = (float4*)out;
    const float4* __restrict__ w4a = (const float4*)(wsm);
    const float4* __restrict__ w4b = (const float4*)(wsm + 1024);
    const float4* __restrict__ w4c = (const float4*)(wsm + 2048);
    const float4* __restrict__ w4d = (const float4*)(wsm + 3072);

    for (int chunk = gw; chunk < NCHUNKS; chunk += nw) {
        const int row0 = chunk * 32;

        // ---------------- Phase 1: h = x @ pre_w.T (32 rows per warp) -----
        float hr0 = 0.f, hr1 = 0.f, hr2 = 0.f, hr3 = 0.f;
        #pragma unroll 1
        for (int s = 0; s < 8; s++) {
            float acc[4][4];
            #pragma unroll
            for (int rr = 0; rr < 4; rr++)
                #pragma unroll
                for (int q = 0; q < 4; q++) acc[rr][q] = 0.f;

            const float4* xb = x4 + (size_t)(row0 + 4 * s) * 256;
            #pragma unroll 2
            for (int k = 0; k < 8; k++) {
                const int idx = lane + 32 * k;
                float4 w0 = w4a[idx], w1 = w4b[idx], w2 = w4c[idx], w3 = w4d[idx];
                #pragma unroll
                for (int rr = 0; rr < 4; rr++) {
                    float4 xv = xb[rr * 256 + idx];
                    acc[rr][0] = fmaf(xv.x, w0.x, fmaf(xv.y, w0.y, fmaf(xv.z, w0.z, fmaf(xv.w, w0.w, acc[rr][0]))));
                    acc[rr][1] = fmaf(xv.x, w1.x, fmaf(xv.y, w1.y, fmaf(xv.z, w1.z, fmaf(xv.w, w1.w, acc[rr][1]))));
                    acc[rr][2] = fmaf(xv.x, w2.x, fmaf(xv.y, w2.y, fmaf(xv.z, w2.z, fmaf(xv.w, w2.w, acc[rr][2]))));
                    acc[rr][3] = fmaf(xv.x, w3.x, fmaf(xv.y, w3.y, fmaf(xv.z, w3.z, fmaf(xv.w, w3.w, acc[rr][3]))));
                }
            }
            // butterfly allreduce of 16 values, then lane (4s+rr) keeps row (4s+rr)
            #pragma unroll
            for (int rr = 0; rr < 4; rr++)
                #pragma unroll
                for (int q = 0; q < 4; q++)
                    #pragma unroll
                    for (int off = 16; off; off >>= 1)
                        acc[rr][q] += __shfl_xor_sync(0xffffffffu, acc[rr][q], off);
            #pragma unroll
            for (int rr = 0; rr < 4; rr++) {
                if (lane == 4 * s + rr) {
                    hr0 = acc[rr][0]; hr1 = acc[rr][1]; hr2 = acc[rr][2]; hr3 = acc[rr][3];
                }
            }
        }

        // ---------------- Phase 2: 4-qubit circuit, one row per lane ------
        const float f0 = tanhf(hr0 + pbq[0]) * PI_F;
        const float f1 = tanhf(hr1 + pbq[1]) * PI_F;
        const float f2 = tanhf(hr2 + pbq[2]) * PI_F;
        const float f3 = tanhf(hr3 + pbq[3]) * PI_F;

        // per-qubit state after RZ(atan(f^2)) RY(atan(f)) H |0>
        auto mkv = [](float fq, c32& v0, c32& v1) {
            // half angle of a = atan(fq), stable: tan(a/2) = fq/(1+sqrt(1+fq^2))
            float u  = f_sqrt(fmaf(fq, fq, 1.f));
            float ta = fq * f_rcp(1.f + u);
            float c1 = f_rsqrt(fmaf(ta, ta, 1.f));
            float s1 = ta * c1;
            // half angle of b = atan(fq^2)
            float g  = fq * fq;
            float u2 = f_sqrt(fmaf(g, g, 1.f));
            float tb = g * f_rcp(1.f + u2);
            float cb = f_rsqrt(fmaf(tb, tb, 1.f));
            float sb = tb * cb;
            const float r2 = 0.7071067811865476f;
            float p = (c1 - s1) * r2;
            float q = (c1 + s1) * r2;
            v0.x = p * cb; v0.y = -p * sb;   // p * e^{-i b/2}
            v1.x = q * cb; v1.y =  q * sb;   // q * e^{+i b/2}
        };
        c32 va0, va1, vb0, vb1, vc0, vc1, vd0, vd1;
        mkv(f0, va0, va1); mkv(f1, vb0, vb1); mkv(f2, vc0, vc1); mkv(f3, vd0, vd1);

        c32 w01[4] = { cmul(va0, vb0), cmul(va0, vb1), cmul(va1, vb0), cmul(va1, vb1) };
        c32 w23[4] = { cmul(vc0, vd0), cmul(vc0, vd1), cmul(vc1, vd0), cmul(vc1, vd1) };
        c32 psi[16];
        #pragma unroll
        for (int j = 0; j < 16; j++) psi[j] = cmul(w01[j >> 2], w23[j & 3]);

        // CNOT ring (index permutations; compile-time)
        {
            c32 tmp[16];
            #pragma unroll
            for (int j = 0; j < 16; j++) tmp[j] = psi[cnotp(j, 0, 1)];
            #pragma unroll
            for (int j = 0; j < 16; j++) psi[j] = tmp[j];
            #pragma unroll
            for (int j = 0; j < 16; j++) tmp[j] = psi[cnotp(j, 1, 2)];
            #pragma unroll
            for (int j = 0; j < 16; j++) psi[j] = tmp[j];
            #pragma unroll
            for (int j = 0; j < 16; j++) tmp[j] = psi[cnotp(j, 2, 3)];
            #pragma unroll
            for (int j = 0; j < 16; j++) psi[j] = tmp[j];
            #pragma unroll
            for (int j = 0; j < 16; j++) tmp[j] = psi[cnotp(j, 3, 0)];
            #pragma unroll
            for (int j = 0; j < 16; j++) psi[j] = tmp[j];
        }

        // Rot gates (constant matrices from smem)
        #pragma unroll
        for (int q = 0; q < 4; q++) {
            float2 m00 = rotm[q][0], m01 = rotm[q][1], m10 = rotm[q][2], m11 = rotm[q][3];
            c32 U00 = {m00.x, m00.y}, U01 = {m01.x, m01.y};
            c32 U10 = {m10.x, m10.y}, U11 = {m11.x, m11.y};
            const int mask = 8 >> q;
            #pragma unroll
            for (int j = 0; j < 16; j++) {
                if ((j & mask) == 0) {
                    const int j1 = j | mask;
                    c32 a = psi[j], b = psi[j1];
                    c32 t0 = cmul(U00, a), t1 = cmul(U01, b);
                    c32 t2 = cmul(U10, a), t3 = cmul(U11, b);
                    psi[j].x  = t0.x + t1.x; psi[j].y  = t0.y + t1.y;
                    psi[j1].x = t2.x + t3.x; psi[j1].y = t2.y + t3.y;
                }
            }
        }

        // z = Z-expectations
        float z0 = 0.f, z1 = 0.f, z2 = 0.f, z3 = 0.f;
        #pragma unroll
        for (int j = 0; j < 16; j++) {
            float p = fmaf(psi[j].x, psi[j].x, psi[j].y * psi[j].y);
            z0 += (j & 8) ? -p : p;
            z1 += (j & 4) ? -p : p;
            z2 += (j & 2) ? -p : p;
            z3 += (j & 1) ? -p : p;
        }
        zsm[warp * 32 + lane] = make_float4(z0, z1, z2, z3);
        __syncwarp();

        // ---------------- Phase 3: out = z @ post_w.T + post_b ------------
        const int zbase = warp * 32;
        #pragma unroll 1
        for (int k = 0; k < 8; k++) {
            const int idx = lane + 32 * k;
            float4 p0 = ((const float4*)pwT)[idx];
            float4 p1 = ((const float4*)(pwT + 1024))[idx];
            float4 p2 = ((const float4*)(pwT + 2048))[idx];
            float4 p3 = ((const float4*)(pwT + 3072))[idx];
            float4 bv = ((const float4*)pbs)[idx];
            float4* orow = out4 + (size_t)row0 * 256 + idx;
            #pragma unroll 4
            for (int r = 0; r < 32; r++) {
                float4 z = zsm[zbase + r];
                float4 o;
                o.x = fmaf(z.x, p0.x, fmaf(z.y, p1.x, fmaf(z.z, p2.x, fmaf(z.w, p3.x, bv.x))));
                o.y = fmaf(z.x, p0.y, fmaf(z.y, p1.y, fmaf(z.z, p2.y, fmaf(z.w, p3.y, bv.y))));
                o.z = fmaf(z.x, p0.z, fmaf(z.y, p1.z, fmaf(z.z, p2.z, fmaf(z.w, p3.z, bv.z))));
                o.w = fmaf(z.x, p0.w, fmaf(z.y, p1.w, fmaf(z.z, p2.w, fmaf(z.w, p3.w, bv.w))));
                orow[(size_t)r * 256] = o;
            }
        }
        __syncwarp();
    }
}

extern "C" void kernel_launch(void* const* d_in, const int* in_sizes, int n_in,
                              void* d_out, int out_size)
{
    const float* x      = (const float*)d_in[0];
    const float* pre_w  = (const float*)d_in[1];
    const float* pre_b  = (const float*)d_in[2];
    const float* qw     = (const float*)d_in[3];
    const float* post_w = (const float*)d_in[4];
    const float* post_b = (const float*)d_in[5];
    float* out          = (float*)d_out;
    (void)in_sizes; (void)n_in; (void)out_size;
    qp_kernel<<<BLOCKS, THREADS>>>(x, pre_w, pre_b, qw, post_w, post_b, out);
}